// round 10
// baseline (speedup 1.0000x reference)
#include <cuda_runtime.h>
#include <cuda_fp16.h>
#include <cstdint>
#include <math.h>

#define BB 4
#define VV 2048
#define TT 12
#define HH 64
#define EE 32768
#define VT (BB*VV)            /* 8192 */
#define TOTK 27
#define KK (TOTK*HH + HH)     /* 1792 */
#define NCONV 7
#define VH (VT*HH)

// ================= helpers =================
__device__ __forceinline__ uint32_t smem_u32(const void* p) {
    uint32_t a;
    asm("{ .reg .u64 t; cvta.to.shared.u64 t, %1; cvt.u32.u64 %0, t; }" : "=r"(a) : "l"(p));
    return a;
}
__device__ __forceinline__ void cp16(uint32_t dst, const void* src) {
    asm volatile("cp.async.ca.shared.global [%0], [%1], 16;" :: "r"(dst), "l"(src));
}
#define CP_COMMIT() asm volatile("cp.async.commit_group;" ::: "memory")
#define CP_WAIT0()  asm volatile("cp.async.wait_group 0;" ::: "memory")
#define BARH(id)    asm volatile("bar.sync %0, 128;" :: "r"((id) + 1) : "memory")

// ================= persistent device scratch =================
__device__ __align__(256) __half          g_FvH[VT * KK];              // 29.4 MB (h-side)
__device__ __align__(256) __half          g_FvX[(size_t)TT * VT * KK]; // 352 MB (x-side)
__device__ __align__(256) __half          g_WtH[NCONV * HH * KK];      // [perm conv][n][k]
__device__ __align__(256) float           g_biasP[NCONV * HH];
__device__ __align__(256) float           g_basis[EE * 8];
__device__ __align__(256) int             g_cell[EE];
// CSR-ordered edge tables
__device__ __align__(256) float           g_basisC[EE * 8];
__device__ __align__(256) int             g_scC[EE];                   // src | (cell<<16)
__device__ __align__(256) int             g_cnt[256 * VV];             // per-slice node counts
__device__ int            g_deg[VV];
__device__ float          g_deginv[VV];
__device__ int            g_csroff[VV + 1];
__device__ __align__(256) float g_h [VH];
__device__ __align__(256) float g_a [VH];
__device__ __align__(256) float g_ho[VH];
__device__ __align__(256) float g_xg[(size_t)TT * 3 * VH];  // [t][rx,zx,nx]

// ---------------- prep: weight pack (fp16) + spline basis/cell + zero h ----------------
__global__ void k_prep(const float* __restrict__ Wk, const float* __restrict__ Wroot,
                       const float* __restrict__ bias, const float* __restrict__ attr) {
    int idx = blockIdx.x * blockDim.x + threadIdx.x;
    if (idx < VH) g_h[idx] = 0.0f;
    if (idx < EE) {
        int e = idx;
        float fr[3]; int lo[3];
        #pragma unroll
        for (int d = 0; d < 3; d++) {
            float u  = attr[e * 3 + d] * 2.0f;
            float fl = fminf(fmaxf(floorf(u), 0.0f), 1.0f);
            fr[d] = u - fl;
            lo[d] = (int)fl;
        }
        #pragma unroll
        for (int s = 0; s < 8; s++) {
            int b0 = s & 1, b1 = (s >> 1) & 1, b2 = (s >> 2) & 1;
            float b = (b0 ? fr[0] : 1.0f - fr[0])
                    * (b1 ? fr[1] : 1.0f - fr[1])
                    * (b2 ? fr[2] : 1.0f - fr[2]);
            g_basis[e * 8 + s] = b;
        }
        g_cell[e] = lo[0] + 2 * lo[1] + 4 * lo[2];
    }
    if (idx >= NCONV * HH * KK) return;
    int k = idx % KK;
    int n = (idx / KK) & 63;
    int p = idx / (KK * HH);
    const int perm[7] = {0, 2, 4, 1, 3, 5, 6};
    int conv = perm[p];
    float v = (k < TOTK * HH) ? Wk[(conv * TOTK * HH + k) * HH + n]
                              : Wroot[(conv * HH + (k - TOTK * HH)) * HH + n];
    g_WtH[idx] = __float2half(v);
    if (k == 0) g_biasP[p * HH + n] = bias[conv * HH + n];
}

// ---------------- setup pass 1: per-slice (128 edges) per-node counts ----------------
__global__ void k_cnt(const int* __restrict__ eidx) {
    int e = blockIdx.x * blockDim.x + threadIdx.x;
    if (e < EE) atomicAdd(&g_cnt[(e >> 7) * VV + eidx[EE + e]], 1);
}

// ---------------- setup pass 2: per-node local prefixes over slices + totals ----------
__global__ void k_offs() {
    int v = blockIdx.x * blockDim.x + threadIdx.x;
    if (v >= VV) return;
    int run = 0;
    for (int bb = 0; bb < 256; bb++) {
        int tv = g_cnt[bb * VV + v];
        g_cnt[bb * VV + v] = run;
        run += tv;
    }
    g_deg[v] = run;
}

// ---------------- setup pass 3: CSR offsets + deginv (single block) ----------------
__global__ void k_scan2() {
    __shared__ int sdeg[VV];
    __shared__ int soff[VV + 1];
    int tid = threadIdx.x;
    for (int v = tid; v < VV; v += blockDim.x) sdeg[v] = g_deg[v];
    __syncthreads();
    if (tid == 0) {
        int a = 0;
        for (int v = 0; v < VV; v++) { soff[v] = a; a += sdeg[v]; }
        soff[VV] = a;
    }
    __syncthreads();
    for (int v = tid; v < VV; v += blockDim.x) {
        g_csroff[v] = soff[v];
        g_deginv[v] = 1.0f / (float)max(sdeg[v], 1);
    }
    if (tid == 0) g_csroff[VV] = soff[VV];
}

// ---------------- setup pass 4: fill tables in exact global edge order ----------------
__global__ void k_fill3(const int* __restrict__ eidx) {
    __shared__ int sbase[VV];
    int bb = blockIdx.x;                       // slice of 128 edges
    for (int v = threadIdx.x; v < VV; v += 256)
        sbase[v] = g_csroff[v] + g_cnt[bb * VV + v];
    __syncthreads();
    if (threadIdx.x >= 32) return;
    int lane = threadIdx.x;
    const int* dst = eidx + EE;
    #pragma unroll
    for (int r = 0; r < 4; r++) {
        int e = bb * 128 + r * 32 + lane;
        int d = dst[e];
        unsigned grp = __match_any_sync(0xFFFFFFFFu, d);
        int leader = __ffs(grp) - 1;
        int rank = __popc(grp & ((1u << lane) - 1u));
        int lb = 0;
        if (lane == leader) lb = sbase[d];
        lb = __shfl_sync(grp, lb, leader);
        int pos = lb + rank;
        if (lane == leader) sbase[d] = lb + __popc(grp);
        g_scC[pos] = eidx[e] | (g_cell[e] << 16);
        *(float4*)&g_basisC[pos * 8]     = *(const float4*)&g_basis[e * 8];
        *(float4*)&g_basisC[pos * 8 + 4] = *(const float4*)&g_basis[e * 8 + 4];
        __syncwarp();
    }
}

// ---------------- scatter: register accumulators + uniform cell switch ----------------
template <int L0, int L1, int L2>
__device__ __forceinline__ void upd(float* acc, const float* bas, float xs) {
    #pragma unroll
    for (int s = 0; s < 8; s++) {
        int k = (L0 + (s & 1)) + 3 * (L1 + ((s >> 1) & 1)) + 9 * (L2 + ((s >> 2) & 1));
        acc[k] = fmaf(bas[s], xs, acc[k]);
    }
}

__global__ void __launch_bounds__(256) k_scatter(const float* __restrict__ feat, int stride,
                                                 __half* __restrict__ dst) {
    int c    = threadIdx.x;
    int nsub = threadIdx.y;
    int node = blockIdx.x * 4 + nsub;
    int b = node >> 11;
    int v = node & (VV - 1);
    feat += (size_t)blockIdx.y * HH;
    dst  += (size_t)blockIdx.y * VT * KK;

    float acc[TOTK];
    #pragma unroll
    for (int k = 0; k < TOTK; k++) acc[k] = 0.0f;

    int i0 = g_csroff[v], i1 = g_csroff[v + 1];
    int base = b * VV;
    for (int ii = i0; ii < i1; ii++) {
        float4 bA = *(const float4*)&g_basisC[ii * 8];
        float4 bB = *(const float4*)&g_basisC[ii * 8 + 4];
        int    sc = g_scC[ii];
        float  xs = feat[(size_t)(base + (sc & 0xFFFF)) * stride + c];
        float bas[8] = {bA.x, bA.y, bA.z, bA.w, bB.x, bB.y, bB.z, bB.w};
        switch (sc >> 16) {
            case 0: upd<0,0,0>(acc, bas, xs); break;
            case 1: upd<1,0,0>(acc, bas, xs); break;
            case 2: upd<0,1,0>(acc, bas, xs); break;
            case 3: upd<1,1,0>(acc, bas, xs); break;
            case 4: upd<0,0,1>(acc, bas, xs); break;
            case 5: upd<1,0,1>(acc, bas, xs); break;
            case 6: upd<0,1,1>(acc, bas, xs); break;
            case 7: upd<1,1,1>(acc, bas, xs); break;
        }
    }
    float di = g_deginv[v];
    __half* o = dst + (size_t)node * KK + c;
    #pragma unroll
    for (int k = 0; k < TOTK; k++) o[k * HH] = __float2half(acc[k] * di);
    o[TOTK * HH] = __float2half(feat[(size_t)node * stride + c]);
}

// ---------------- FP16 mma GEMM: M=32 tiles, 256 thr, intra-CTA split-K ----------------
// EPI: 0 plain(+bias), 1 elu(+bias), 2 extra+tanh(+bias), 3 fused GRU gates (NG==2).
template <int NG, int EPI, int BATCH>
__global__ void __launch_bounds__(256) k_gemm(const __half* __restrict__ Ab,
                                              const __half* __restrict__ Bw,
                                              const float* __restrict__ bias,
                                              const float* __restrict__ extra,
                                              const float* __restrict__ xgt,
                                              float* __restrict__ out, int t) {
    extern __shared__ __half smem[];
    const int ABUF = 32 * 40;
    const int BBUF = NG * 64 * 40;

    const int tid  = threadIdx.x;
    const int half = tid >> 7;
    const int htid = tid & 127;
    const int m0   = blockIdx.x * 32;
    const int lane = tid & 31, wid = (tid >> 5) & 3;
    const int wn = wid * 16;
    const int g  = lane >> 2,  tq = lane & 3;

    __half* As = smem + half * (2 * ABUF);
    __half* Bs = smem + 4 * ABUF + half * (2 * BBUF);

    float c[NG][2][2][4];
    #pragma unroll
    for (int gg = 0; gg < NG; gg++)
        #pragma unroll
        for (int mt = 0; mt < 2; mt++)
            #pragma unroll
            for (int nt = 0; nt < 2; nt++)
                #pragma unroll
                for (int i = 0; i < 4; i++) c[gg][mt][nt][i] = 0.0f;

    const uint32_t sA = smem_u32(As);
    const uint32_t sB = smem_u32(Bs);

    auto load_tiles = [&](int kc, int st) {
        {   // A tile: 32 rows x 4 segs = 128 segs
            int row = htid >> 2, so = htid & 3;
            cp16(sA + (uint32_t)(st * ABUF + row * 40 + so * 8) * 2,
                 &Ab[(size_t)(m0 + row) * KK + kc * 32 + so * 8]);
        }
        #pragma unroll
        for (int i = 0; i < NG * 2; i++) {    // B: NG*64 rows x 4 segs
            int seg = htid + i * 128;
            int row = seg >> 2, so = seg & 3;
            cp16(sB + (uint32_t)(st * BBUF + row * 40 + so * 8) * 2,
                 &Bw[(size_t)row * KK + kc * 32 + so * 8]);
        }
    };

    const int NIT = (KK / 32) / 2;   // 28 chunks per half
    load_tiles(half, 0);
    CP_COMMIT();

    for (int it = 0; it < NIT; it++) {
        const int ck = half + 2 * it;
        CP_WAIT0();
        BARH(half);
        if (it + 1 < NIT) { load_tiles(ck + 2, (it + 1) & 1); CP_COMMIT(); }
        const int buf = it & 1;
        #pragma unroll
        for (int kh = 0; kh < 2; kh++) {
            const int kb = kh * 16;
            uint32_t a[2][4];
            #pragma unroll
            for (int mt = 0; mt < 2; mt++) {
                int r0 = buf * ABUF + (mt * 16 + g) * 40 + kb + 2 * tq;
                int r1 = r0 + 8 * 40;
                a[mt][0] = *(const uint32_t*)&As[r0];
                a[mt][1] = *(const uint32_t*)&As[r1];
                a[mt][2] = *(const uint32_t*)&As[r0 + 8];
                a[mt][3] = *(const uint32_t*)&As[r1 + 8];
            }
            #pragma unroll
            for (int gg = 0; gg < NG; gg++) {
                uint32_t b[2][2];
                #pragma unroll
                for (int nt = 0; nt < 2; nt++) {
                    int br = buf * BBUF + (gg * 64 + wn + nt * 8 + g) * 40 + kb + 2 * tq;
                    b[nt][0] = *(const uint32_t*)&Bs[br];
                    b[nt][1] = *(const uint32_t*)&Bs[br + 8];
                }
                #pragma unroll
                for (int mt = 0; mt < 2; mt++)
                    #pragma unroll
                    for (int nt = 0; nt < 2; nt++) {
                        float* cc = c[gg][mt][nt];
                        asm volatile(
                            "mma.sync.aligned.m16n8k16.row.col.f32.f16.f16.f32 "
                            "{%0,%1,%2,%3},{%4,%5,%6,%7},{%8,%9},{%0,%1,%2,%3};"
                            : "+f"(cc[0]), "+f"(cc[1]), "+f"(cc[2]), "+f"(cc[3])
                            : "r"(a[mt][0]), "r"(a[mt][1]), "r"(a[mt][2]), "r"(a[mt][3]),
                              "r"(b[nt][0]), "r"(b[nt][1]));
                    }
            }
        }
        BARH(half);
    }

    // ---- cross-half reduction ----
    __syncthreads();
    float* red = (float*)smem;
    const int RP = 16 * NG + 1;
    if (half == 1) {
        float* r = &red[htid * RP];
        int ix = 0;
        #pragma unroll
        for (int gg = 0; gg < NG; gg++)
            #pragma unroll
            for (int mt = 0; mt < 2; mt++)
                #pragma unroll
                for (int nt = 0; nt < 2; nt++)
                    #pragma unroll
                    for (int i = 0; i < 4; i++) r[ix++] = c[gg][mt][nt][i];
    }
    __syncthreads();
    if (half == 1) return;
    {
        const float* r = &red[htid * RP];
        int ix = 0;
        #pragma unroll
        for (int gg = 0; gg < NG; gg++)
            #pragma unroll
            for (int mt = 0; mt < 2; mt++)
                #pragma unroll
                for (int nt = 0; nt < 2; nt++)
                    #pragma unroll
                    for (int i = 0; i < 4; i++) c[gg][mt][nt][i] += r[ix++];
    }

    // ---- epilogue ----
    if constexpr (EPI == 3) {
        // fused GRU gates: gg0 = hr (conv1), gg1 = zh (conv3)
        #pragma unroll
        for (int mt = 0; mt < 2; mt++) {
            #pragma unroll
            for (int nt = 0; nt < 2; nt++) {
                int col = wn + nt * 8 + 2 * tq;
                float b00 = bias[col], b01 = bias[col + 1];
                float b10 = bias[64 + col], b11 = bias[64 + col + 1];
                #pragma unroll
                for (int hf = 0; hf < 2; hf++) {
                    int row = m0 + mt * 16 + g + hf * 8;
                    int o2  = row * 64 + col;
                    float hr0 = c[0][mt][nt][hf * 2 + 0] + b00;
                    float hr1 = c[0][mt][nt][hf * 2 + 1] + b01;
                    float zh0 = c[1][mt][nt][hf * 2 + 0] + b10;
                    float zh1 = c[1][mt][nt][hf * 2 + 1] + b11;
                    float2 rx = *(const float2*)&xgt[o2];
                    float2 zx = *(const float2*)&xgt[VH + o2];
                    float2 nx = *(const float2*)&xgt[2 * VH + o2];
                    float2 ho = *(const float2*)&extra[o2];
                    float r0 = 1.0f / (1.0f + expf(-(rx.x + hr0)));
                    float r1 = 1.0f / (1.0f + expf(-(rx.y + hr1)));
                    float z0 = 1.0f / (1.0f + expf(-(zx.x + zh0)));
                    float z1 = 1.0f / (1.0f + expf(-(zx.y + zh1)));
                    float n0 = tanhf(nx.x + r0 * hr0);
                    float n1 = tanhf(nx.y + r1 * hr1);
                    float h0 = (1.0f - z0) * n0 + z0 * ho.x;
                    float h1 = (1.0f - z1) * n1 + z1 * ho.y;
                    *(float2*)&g_h[o2] = make_float2(h0, h1);
                    *(float2*)&out[((size_t)row * TT + t) * HH + col] = make_float2(h0, h1);
                }
            }
        }
    } else {
        #pragma unroll
        for (int gg = 0; gg < NG; gg++) {
            const float* biasg = bias + gg * 64;
            #pragma unroll
            for (int mt = 0; mt < 2; mt++) {
                #pragma unroll
                for (int nt = 0; nt < 2; nt++) {
                    int col = wn + nt * 8 + 2 * tq;
                    float b0 = biasg[col], b1 = biasg[col + 1];
                    #pragma unroll
                    for (int hf = 0; hf < 2; hf++) {
                        int row = m0 + mt * 16 + g + hf * 8;
                        float v0 = c[gg][mt][nt][hf * 2 + 0] + b0;
                        float v1 = c[gg][mt][nt][hf * 2 + 1] + b1;
                        if (EPI == 1) {
                            v0 = (v0 > 0.0f) ? v0 : (expf(v0) - 1.0f);
                            v1 = (v1 > 0.0f) ? v1 : (expf(v1) - 1.0f);
                        }
                        size_t o;
                        if (BATCH) {
                            int tb = row >> 13, nd = row & (VT - 1);
                            o = ((size_t)(tb * NG + gg) * VT + nd) * 64 + col;
                        } else {
                            o = (size_t)gg * VH + (size_t)row * 64 + col;
                        }
                        if (EPI == 2) {
                            float2 e2 = *(const float2*)&extra[(size_t)row * 64 + col];
                            v0 = e2.x + tanhf(v0);
                            v1 = e2.y + tanhf(v1);
                        }
                        *(float2*)&out[o] = make_float2(v0, v1);
                    }
                }
            }
        }
    }
}

// ---------------- launch ----------------
extern "C" void kernel_launch(void* const* d_in, const int* in_sizes, int n_in,
                              void* d_out, int out_size) {
    const float* x     = (const float*)d_in[0];
    const float* attr  = (const float*)d_in[1];
    const float* Wk    = (const float*)d_in[2];
    const float* Wroot = (const float*)d_in[3];
    const float* bias  = (const float*)d_in[4];
    const int*   eidx  = (const int*)d_in[5];
    float*       out   = (float*)d_out;

    __half *pWt, *pFvH, *pFvX;
    float *pBias, *pH, *pA, *pHO, *pXG;
    int   *pCnt;
    cudaGetSymbolAddress((void**)&pWt,   g_WtH);
    cudaGetSymbolAddress((void**)&pFvH,  g_FvH);
    cudaGetSymbolAddress((void**)&pFvX,  g_FvX);
    cudaGetSymbolAddress((void**)&pBias, g_biasP);
    cudaGetSymbolAddress((void**)&pH,    g_h);
    cudaGetSymbolAddress((void**)&pA,    g_a);
    cudaGetSymbolAddress((void**)&pHO,   g_ho);
    cudaGetSymbolAddress((void**)&pXG,   g_xg);
    cudaGetSymbolAddress((void**)&pCnt,  g_cnt);

    const int SM1 = 10240 + 20480 * 1;   // 30720
    const int SM2 = 10240 + 20480 * 2;   // 51200
    const int SM3 = 10240 + 20480 * 3;   // 71680
    cudaFuncSetAttribute(k_gemm<1, 1, 0>, cudaFuncAttributeMaxDynamicSharedMemorySize, SM1);
    cudaFuncSetAttribute(k_gemm<1, 2, 0>, cudaFuncAttributeMaxDynamicSharedMemorySize, SM1);
    cudaFuncSetAttribute(k_gemm<2, 3, 0>, cudaFuncAttributeMaxDynamicSharedMemorySize, SM2);
    cudaFuncSetAttribute(k_gemm<3, 0, 1>, cudaFuncAttributeMaxDynamicSharedMemorySize, SM3);

    // ---- setup (every call; deterministic) ----
    cudaMemsetAsync(pCnt, 0, 256 * VV * sizeof(int));
    k_prep <<<(NCONV * HH * KK + 255) / 256, 256>>>(Wk, Wroot, bias, attr);
    k_cnt  <<<EE / 256, 256>>>(eidx);
    k_offs <<<VV / 256, 256>>>();
    k_scan2<<<1, 1024>>>();
    k_fill3<<<256, 256>>>(eidx);

    // ---- fork: x-side (scatter + batched GEMM) in 4 chunks of 3 timesteps ----
    cudaStream_t s1;
    cudaStreamCreateWithFlags(&s1, cudaStreamNonBlocking);
    cudaEvent_t evF, ev[4];
    cudaEventCreateWithFlags(&evF, cudaEventDisableTiming);
    for (int i = 0; i < 4; i++) cudaEventCreateWithFlags(&ev[i], cudaEventDisableTiming);

    cudaEventRecord(evF, 0);
    cudaStreamWaitEvent(s1, evF, 0);

    const dim3 sblk(64, 4);
    const int  HK = HH * KK;
    const int  GG = VT / 32;     // 256

    for (int cch = 0; cch < 4; cch++) {
        k_scatter<<<dim3(VT / 4, 3), sblk, 0, s1>>>(x + cch * 3 * HH, TT * HH,
                                                    pFvX + (size_t)cch * 3 * VT * KK);
        k_gemm<3, 0, 1><<<GG * 3, 256, SM3, s1>>>(pFvX + (size_t)cch * 3 * VT * KK, pWt,
                                                  pBias, nullptr, nullptr,
                                                  pXG + (size_t)cch * 9 * VH, 0);
        cudaEventRecord(ev[cch], s1);
    }

    // ---- recurrent h-loop (main stream) ----
    for (int t = 0; t < TT; t++) {
        // ODE: a = elu(conv5(h)) ; ho = h + tanh(conv6(a))
        k_scatter<<<dim3(VT / 4, 1), sblk>>>(pH, HH, pFvH);
        k_gemm<1, 1, 0><<<GG, 256, SM1>>>(pFvH, pWt + 5 * HK, pBias + 5 * HH,
                                          nullptr, nullptr, pA, 0);
        k_scatter<<<dim3(VT / 4, 1), sblk>>>(pA, HH, pFvH);
        k_gemm<1, 2, 0><<<GG, 256, SM1>>>(pFvH, pWt + 6 * HK, pBias + 6 * HH,
                                          pH, nullptr, pHO, 0);
        // GRU: [hr|zh] = conv{1,3}(ho), gates fused in epilogue -> g_h + out
        k_scatter<<<dim3(VT / 4, 1), sblk>>>(pHO, HH, pFvH);
        if ((t % 3) == 0) cudaStreamWaitEvent(0, ev[t / 3], 0);
        k_gemm<2, 3, 0><<<GG, 256, SM2>>>(pFvH, pWt + 3 * HK, pBias + 3 * HH,
                                          pHO, pXG + (size_t)t * 3 * VH, out, t);
    }
}

// round 11
// speedup vs baseline: 1.1788x; 1.1788x over previous
#include <cuda_runtime.h>
#include <cuda_fp16.h>
#include <cstdint>
#include <math.h>

#define BB 4
#define VV 2048
#define TT 12
#define HH 64
#define EE 32768
#define VT (BB*VV)            /* 8192 */
#define TOTK 27
#define KK (TOTK*HH + HH)     /* 1792 */
#define NCONV 7
#define VH (VT*HH)

// ================= helpers =================
__device__ __forceinline__ uint32_t smem_u32(const void* p) {
    uint32_t a;
    asm("{ .reg .u64 t; cvta.to.shared.u64 t, %1; cvt.u32.u64 %0, t; }" : "=r"(a) : "l"(p));
    return a;
}
__device__ __forceinline__ void cp16(uint32_t dst, const void* src) {
    asm volatile("cp.async.ca.shared.global [%0], [%1], 16;" :: "r"(dst), "l"(src));
}
#define CP_COMMIT() asm volatile("cp.async.commit_group;" ::: "memory")
#define CP_WAIT0()  asm volatile("cp.async.wait_group 0;" ::: "memory")
#define BARH(id)    asm volatile("bar.sync %0, 128;" :: "r"((id) + 1) : "memory")

// ================= persistent device scratch =================
__device__ __align__(256) __half          g_FvH[VT * KK];              // 29.4 MB (h-side)
__device__ __align__(256) __half          g_FvX[(size_t)TT * VT * KK]; // 352 MB (x-side)
__device__ __align__(256) __half          g_WtH[NCONV * HH * KK];      // [perm conv][n][k]
__device__ __align__(256) float           g_biasP[NCONV * HH];
__device__ __align__(256) float           g_basis[EE * 8];
__device__ __align__(256) int             g_cell[EE];
// CSR-ordered edge tables
__device__ __align__(256) float           g_basisC[EE * 8];
__device__ __align__(256) int             g_scC[EE];                   // src | (cell<<16)
__device__ __align__(256) int             g_cnt[256 * VV];             // per-slice node counts
__device__ int            g_deg[VV];
__device__ float          g_deginv[VV];
__device__ int            g_csroff[VV + 1];
__device__ __align__(256) float g_h [VH];
__device__ __align__(256) float g_a [VH];
__device__ __align__(256) float g_ho[VH];
__device__ __align__(256) float g_xg[(size_t)TT * 3 * VH];  // [t][rx,zx,nx]

// ---------------- prep: weight pack (fp16) + spline basis/cell + zero h ----------------
__global__ void k_prep(const float* __restrict__ Wk, const float* __restrict__ Wroot,
                       const float* __restrict__ bias, const float* __restrict__ attr) {
    int idx = blockIdx.x * blockDim.x + threadIdx.x;
    if (idx < VH) g_h[idx] = 0.0f;
    if (idx < EE) {
        int e = idx;
        float fr[3]; int lo[3];
        #pragma unroll
        for (int d = 0; d < 3; d++) {
            float u  = attr[e * 3 + d] * 2.0f;
            float fl = fminf(fmaxf(floorf(u), 0.0f), 1.0f);
            fr[d] = u - fl;
            lo[d] = (int)fl;
        }
        #pragma unroll
        for (int s = 0; s < 8; s++) {
            int b0 = s & 1, b1 = (s >> 1) & 1, b2 = (s >> 2) & 1;
            float b = (b0 ? fr[0] : 1.0f - fr[0])
                    * (b1 ? fr[1] : 1.0f - fr[1])
                    * (b2 ? fr[2] : 1.0f - fr[2]);
            g_basis[e * 8 + s] = b;
        }
        g_cell[e] = lo[0] + 2 * lo[1] + 4 * lo[2];
    }
    if (idx >= NCONV * HH * KK) return;
    int k = idx % KK;
    int n = (idx / KK) & 63;
    int p = idx / (KK * HH);
    const int perm[7] = {0, 2, 4, 1, 3, 5, 6};
    int conv = perm[p];
    float v = (k < TOTK * HH) ? Wk[(conv * TOTK * HH + k) * HH + n]
                              : Wroot[(conv * HH + (k - TOTK * HH)) * HH + n];
    g_WtH[idx] = __float2half(v);
    if (k == 0) g_biasP[p * HH + n] = bias[conv * HH + n];
}

// ---------------- setup pass 1: per-slice (128 edges) per-node counts ----------------
__global__ void k_cnt(const int* __restrict__ eidx) {
    int e = blockIdx.x * blockDim.x + threadIdx.x;
    if (e < EE) atomicAdd(&g_cnt[(e >> 7) * VV + eidx[EE + e]], 1);
}

// ---------------- setup pass 2: per-node local prefixes over slices + totals ----------
__global__ void k_offs() {
    int v = blockIdx.x * blockDim.x + threadIdx.x;
    if (v >= VV) return;
    int run = 0;
    for (int bb = 0; bb < 256; bb++) {
        int tv = g_cnt[bb * VV + v];
        g_cnt[bb * VV + v] = run;
        run += tv;
    }
    g_deg[v] = run;
}

// ---------------- setup pass 3: CSR offsets + deginv (single block) ----------------
__global__ void k_scan2() {
    __shared__ int sdeg[VV];
    __shared__ int soff[VV + 1];
    int tid = threadIdx.x;
    for (int v = tid; v < VV; v += blockDim.x) sdeg[v] = g_deg[v];
    __syncthreads();
    if (tid == 0) {
        int a = 0;
        for (int v = 0; v < VV; v++) { soff[v] = a; a += sdeg[v]; }
        soff[VV] = a;
    }
    __syncthreads();
    for (int v = tid; v < VV; v += blockDim.x) {
        g_csroff[v] = soff[v];
        g_deginv[v] = 1.0f / (float)max(sdeg[v], 1);
    }
    if (tid == 0) g_csroff[VV] = soff[VV];
}

// ---------------- setup pass 4: fill tables in exact global edge order ----------------
__global__ void k_fill3(const int* __restrict__ eidx) {
    __shared__ int sbase[VV];
    int bb = blockIdx.x;                       // slice of 128 edges
    for (int v = threadIdx.x; v < VV; v += 256)
        sbase[v] = g_csroff[v] + g_cnt[bb * VV + v];
    __syncthreads();
    if (threadIdx.x >= 32) return;
    int lane = threadIdx.x;
    const int* dst = eidx + EE;
    #pragma unroll
    for (int r = 0; r < 4; r++) {
        int e = bb * 128 + r * 32 + lane;
        int d = dst[e];
        unsigned grp = __match_any_sync(0xFFFFFFFFu, d);
        int leader = __ffs(grp) - 1;
        int rank = __popc(grp & ((1u << lane) - 1u));
        int lb = 0;
        if (lane == leader) lb = sbase[d];
        lb = __shfl_sync(grp, lb, leader);
        int pos = lb + rank;
        if (lane == leader) sbase[d] = lb + __popc(grp);
        g_scC[pos] = eidx[e] | (g_cell[e] << 16);
        *(float4*)&g_basisC[pos * 8]     = *(const float4*)&g_basis[e * 8];
        *(float4*)&g_basisC[pos * 8 + 4] = *(const float4*)&g_basis[e * 8 + 4];
        __syncwarp();
    }
}

// ---------------- scatter: register accumulators + uniform cell switch ----------------
template <int L0, int L1, int L2>
__device__ __forceinline__ void upd(float* acc, const float* bas, float xs) {
    #pragma unroll
    for (int s = 0; s < 8; s++) {
        int k = (L0 + (s & 1)) + 3 * (L1 + ((s >> 1) & 1)) + 9 * (L2 + ((s >> 2) & 1));
        acc[k] = fmaf(bas[s], xs, acc[k]);
    }
}

__global__ void __launch_bounds__(256) k_scatter(const float* __restrict__ feat, int stride,
                                                 __half* __restrict__ dst) {
    int c    = threadIdx.x;
    int nsub = threadIdx.y;
    int node = blockIdx.x * 4 + nsub;
    int b = node >> 11;
    int v = node & (VV - 1);
    feat += (size_t)blockIdx.y * HH;
    dst  += (size_t)blockIdx.y * VT * KK;

    float acc[TOTK];
    #pragma unroll
    for (int k = 0; k < TOTK; k++) acc[k] = 0.0f;

    int i0 = g_csroff[v], i1 = g_csroff[v + 1];
    int base = b * VV;
    for (int ii = i0; ii < i1; ii++) {
        float4 bA = *(const float4*)&g_basisC[ii * 8];
        float4 bB = *(const float4*)&g_basisC[ii * 8 + 4];
        int    sc = g_scC[ii];
        float  xs = feat[(size_t)(base + (sc & 0xFFFF)) * stride + c];
        float bas[8] = {bA.x, bA.y, bA.z, bA.w, bB.x, bB.y, bB.z, bB.w};
        switch (sc >> 16) {
            case 0: upd<0,0,0>(acc, bas, xs); break;
            case 1: upd<1,0,0>(acc, bas, xs); break;
            case 2: upd<0,1,0>(acc, bas, xs); break;
            case 3: upd<1,1,0>(acc, bas, xs); break;
            case 4: upd<0,0,1>(acc, bas, xs); break;
            case 5: upd<1,0,1>(acc, bas, xs); break;
            case 6: upd<0,1,1>(acc, bas, xs); break;
            case 7: upd<1,1,1>(acc, bas, xs); break;
        }
    }
    float di = g_deginv[v];
    __half* o = dst + (size_t)node * KK + c;
    #pragma unroll
    for (int k = 0; k < TOTK; k++) o[k * HH] = __float2half(acc[k] * di);
    o[TOTK * HH] = __float2half(feat[(size_t)node * stride + c]);
}

// ---------------- FP16 mma GEMM: M=64 tiles, 256 thr, intra-CTA split-K ----------------
// Half p handles K-chunks ck ≡ p (mod 2); warp tile 32x32 (2x2 warps per half).
// EPI: 0 plain(+bias), 1 elu(+bias), 2 extra+tanh(+bias), 3 fused GRU gates (NG==2).
template <int NG, int EPI, int BATCH>
__global__ void __launch_bounds__(256) k_gemm(const __half* __restrict__ Ab,
                                              const __half* __restrict__ Bw,
                                              const float* __restrict__ bias,
                                              const float* __restrict__ extra,
                                              const float* __restrict__ xgt,
                                              float* __restrict__ out, int t) {
    extern __shared__ __half smem[];
    const int ABUF = 64 * 40;
    const int BBUF = NG * 64 * 40;

    const int tid  = threadIdx.x;
    const int half = tid >> 7;
    const int htid = tid & 127;
    const int m0   = blockIdx.x * 64;
    const int lane = tid & 31, wid = (tid >> 5) & 3;
    const int wm = (wid & 1) * 32, wn = (wid >> 1) * 32;
    const int g  = lane >> 2,  tq = lane & 3;

    __half* As = smem + half * (2 * ABUF);
    __half* Bs = smem + 4 * ABUF + half * (2 * BBUF);

    float c[NG][2][4][4];
    #pragma unroll
    for (int gg = 0; gg < NG; gg++)
        #pragma unroll
        for (int mt = 0; mt < 2; mt++)
            #pragma unroll
            for (int nt = 0; nt < 4; nt++)
                #pragma unroll
                for (int i = 0; i < 4; i++) c[gg][mt][nt][i] = 0.0f;

    const uint32_t sA = smem_u32(As);
    const uint32_t sB = smem_u32(Bs);

    auto load_tiles = [&](int kc, int st) {
        #pragma unroll
        for (int i = 0; i < 2; i++) {
            int seg = htid + i * 128;
            int row = seg >> 2, so = seg & 3;
            cp16(sA + (uint32_t)(st * ABUF + row * 40 + so * 8) * 2,
                 &Ab[(size_t)(m0 + row) * KK + kc * 32 + so * 8]);
        }
        #pragma unroll
        for (int i = 0; i < NG * 2; i++) {
            int seg = htid + i * 128;
            int row = seg >> 2, so = seg & 3;
            cp16(sB + (uint32_t)(st * BBUF + row * 40 + so * 8) * 2,
                 &Bw[(size_t)row * KK + kc * 32 + so * 8]);
        }
    };

    const int NIT = (KK / 32) / 2;   // 28 chunks per half
    load_tiles(half, 0);
    CP_COMMIT();

    for (int it = 0; it < NIT; it++) {
        const int ck = half + 2 * it;
        CP_WAIT0();
        BARH(half);
        if (it + 1 < NIT) { load_tiles(ck + 2, (it + 1) & 1); CP_COMMIT(); }
        const int buf = it & 1;
        #pragma unroll
        for (int kh = 0; kh < 2; kh++) {
            const int kb = kh * 16;
            uint32_t a[2][4];
            #pragma unroll
            for (int mt = 0; mt < 2; mt++) {
                int r0 = buf * ABUF + (wm + mt * 16 + g) * 40 + kb + 2 * tq;
                int r1 = r0 + 8 * 40;
                a[mt][0] = *(const uint32_t*)&As[r0];
                a[mt][1] = *(const uint32_t*)&As[r1];
                a[mt][2] = *(const uint32_t*)&As[r0 + 8];
                a[mt][3] = *(const uint32_t*)&As[r1 + 8];
            }
            #pragma unroll
            for (int gg = 0; gg < NG; gg++) {
                uint32_t b[4][2];
                #pragma unroll
                for (int nt = 0; nt < 4; nt++) {
                    int br = buf * BBUF + (gg * 64 + wn + nt * 8 + g) * 40 + kb + 2 * tq;
                    b[nt][0] = *(const uint32_t*)&Bs[br];
                    b[nt][1] = *(const uint32_t*)&Bs[br + 8];
                }
                #pragma unroll
                for (int mt = 0; mt < 2; mt++)
                    #pragma unroll
                    for (int nt = 0; nt < 4; nt++) {
                        float* cc = c[gg][mt][nt];
                        asm volatile(
                            "mma.sync.aligned.m16n8k16.row.col.f32.f16.f16.f32 "
                            "{%0,%1,%2,%3},{%4,%5,%6,%7},{%8,%9},{%0,%1,%2,%3};"
                            : "+f"(cc[0]), "+f"(cc[1]), "+f"(cc[2]), "+f"(cc[3])
                            : "r"(a[mt][0]), "r"(a[mt][1]), "r"(a[mt][2]), "r"(a[mt][3]),
                              "r"(b[nt][0]), "r"(b[nt][1]));
                    }
            }
        }
        BARH(half);
    }

    // ---- cross-half reduction (padded stage: stride 32*NG+1 -> conflict-free) ----
    __syncthreads();
    float* red = (float*)smem;
    const int RP = 32 * NG + 1;
    if (half == 1) {
        float* r = &red[htid * RP];
        int ix = 0;
        #pragma unroll
        for (int gg = 0; gg < NG; gg++)
            #pragma unroll
            for (int mt = 0; mt < 2; mt++)
                #pragma unroll
                for (int nt = 0; nt < 4; nt++)
                    #pragma unroll
                    for (int i = 0; i < 4; i++) r[ix++] = c[gg][mt][nt][i];
    }
    __syncthreads();
    if (half == 1) return;
    {
        const float* r = &red[htid * RP];
        int ix = 0;
        #pragma unroll
        for (int gg = 0; gg < NG; gg++)
            #pragma unroll
            for (int mt = 0; mt < 2; mt++)
                #pragma unroll
                for (int nt = 0; nt < 4; nt++)
                    #pragma unroll
                    for (int i = 0; i < 4; i++) c[gg][mt][nt][i] += r[ix++];
    }

    // ---- epilogue (half 0 only) ----
    if constexpr (EPI == 3) {
        // fused GRU gates: gg0 = hr (conv1), gg1 = zh (conv3)
        #pragma unroll
        for (int mt = 0; mt < 2; mt++) {
            #pragma unroll
            for (int nt = 0; nt < 4; nt++) {
                int col = wn + nt * 8 + 2 * tq;
                float b00 = bias[col], b01 = bias[col + 1];
                float b10 = bias[64 + col], b11 = bias[64 + col + 1];
                #pragma unroll
                for (int hf = 0; hf < 2; hf++) {
                    int row = m0 + wm + mt * 16 + g + hf * 8;
                    int o2  = row * 64 + col;
                    float hr0 = c[0][mt][nt][hf * 2 + 0] + b00;
                    float hr1 = c[0][mt][nt][hf * 2 + 1] + b01;
                    float zh0 = c[1][mt][nt][hf * 2 + 0] + b10;
                    float zh1 = c[1][mt][nt][hf * 2 + 1] + b11;
                    float2 rx = *(const float2*)&xgt[o2];
                    float2 zx = *(const float2*)&xgt[VH + o2];
                    float2 nx = *(const float2*)&xgt[2 * VH + o2];
                    float2 ho = *(const float2*)&extra[o2];
                    float r0 = 1.0f / (1.0f + expf(-(rx.x + hr0)));
                    float r1 = 1.0f / (1.0f + expf(-(rx.y + hr1)));
                    float z0 = 1.0f / (1.0f + expf(-(zx.x + zh0)));
                    float z1 = 1.0f / (1.0f + expf(-(zx.y + zh1)));
                    float n0 = tanhf(nx.x + r0 * hr0);
                    float n1 = tanhf(nx.y + r1 * hr1);
                    float h0 = (1.0f - z0) * n0 + z0 * ho.x;
                    float h1 = (1.0f - z1) * n1 + z1 * ho.y;
                    *(float2*)&g_h[o2] = make_float2(h0, h1);
                    *(float2*)&out[((size_t)row * TT + t) * HH + col] = make_float2(h0, h1);
                }
            }
        }
    } else {
        #pragma unroll
        for (int gg = 0; gg < NG; gg++) {
            const float* biasg = bias + gg * 64;
            #pragma unroll
            for (int mt = 0; mt < 2; mt++) {
                #pragma unroll
                for (int nt = 0; nt < 4; nt++) {
                    int col = wn + nt * 8 + 2 * tq;
                    float b0 = biasg[col], b1 = biasg[col + 1];
                    #pragma unroll
                    for (int hf = 0; hf < 2; hf++) {
                        int row = m0 + wm + mt * 16 + g + hf * 8;
                        float v0 = c[gg][mt][nt][hf * 2 + 0] + b0;
                        float v1 = c[gg][mt][nt][hf * 2 + 1] + b1;
                        if (EPI == 1) {
                            v0 = (v0 > 0.0f) ? v0 : (expf(v0) - 1.0f);
                            v1 = (v1 > 0.0f) ? v1 : (expf(v1) - 1.0f);
                        }
                        size_t o;
                        if (BATCH) {
                            int tb = row >> 13, nd = row & (VT - 1);
                            o = ((size_t)(tb * NG + gg) * VT + nd) * 64 + col;
                        } else {
                            o = (size_t)gg * VH + (size_t)row * 64 + col;
                        }
                        if (EPI == 2) {
                            float2 e2 = *(const float2*)&extra[(size_t)row * 64 + col];
                            v0 = e2.x + tanhf(v0);
                            v1 = e2.y + tanhf(v1);
                        }
                        *(float2*)&out[o] = make_float2(v0, v1);
                    }
                }
            }
        }
    }
}

// ---------------- launch ----------------
extern "C" void kernel_launch(void* const* d_in, const int* in_sizes, int n_in,
                              void* d_out, int out_size) {
    const float* x     = (const float*)d_in[0];
    const float* attr  = (const float*)d_in[1];
    const float* Wk    = (const float*)d_in[2];
    const float* Wroot = (const float*)d_in[3];
    const float* bias  = (const float*)d_in[4];
    const int*   eidx  = (const int*)d_in[5];
    float*       out   = (float*)d_out;

    __half *pWt, *pFvH, *pFvX;
    float *pBias, *pH, *pA, *pHO, *pXG;
    int   *pCnt;
    cudaGetSymbolAddress((void**)&pWt,   g_WtH);
    cudaGetSymbolAddress((void**)&pFvH,  g_FvH);
    cudaGetSymbolAddress((void**)&pFvX,  g_FvX);
    cudaGetSymbolAddress((void**)&pBias, g_biasP);
    cudaGetSymbolAddress((void**)&pH,    g_h);
    cudaGetSymbolAddress((void**)&pA,    g_a);
    cudaGetSymbolAddress((void**)&pHO,   g_ho);
    cudaGetSymbolAddress((void**)&pXG,   g_xg);
    cudaGetSymbolAddress((void**)&pCnt,  g_cnt);

    // smem: 4 A stages + 4 B stages (2 per half), halfs -> bytes
    const int SM1 = (4 * 64 * 40 + 4 * 1 * 64 * 40) * 2;   // 40960
    const int SM2 = (4 * 64 * 40 + 4 * 2 * 64 * 40) * 2;   // 61440
    const int SM3 = (4 * 64 * 40 + 4 * 3 * 64 * 40) * 2;   // 81920
    cudaFuncSetAttribute(k_gemm<1, 1, 0>, cudaFuncAttributeMaxDynamicSharedMemorySize, SM1);
    cudaFuncSetAttribute(k_gemm<1, 2, 0>, cudaFuncAttributeMaxDynamicSharedMemorySize, SM1);
    cudaFuncSetAttribute(k_gemm<2, 3, 0>, cudaFuncAttributeMaxDynamicSharedMemorySize, SM2);
    cudaFuncSetAttribute(k_gemm<3, 0, 1>, cudaFuncAttributeMaxDynamicSharedMemorySize, SM3);

    // ---- setup (every call; deterministic) ----
    cudaMemsetAsync(pCnt, 0, 256 * VV * sizeof(int));
    k_prep <<<(NCONV * HH * KK + 255) / 256, 256>>>(Wk, Wroot, bias, attr);
    k_cnt  <<<EE / 256, 256>>>(eidx);
    k_offs <<<VV / 256, 256>>>();
    k_scan2<<<1, 1024>>>();
    k_fill3<<<256, 256>>>(eidx);

    // ---- fork: x-side (scatter + batched GEMM) in 4 chunks of 3 timesteps ----
    cudaStream_t s1;
    cudaStreamCreateWithFlags(&s1, cudaStreamNonBlocking);
    cudaEvent_t evF, ev[4];
    cudaEventCreateWithFlags(&evF, cudaEventDisableTiming);
    for (int i = 0; i < 4; i++) cudaEventCreateWithFlags(&ev[i], cudaEventDisableTiming);

    cudaEventRecord(evF, 0);
    cudaStreamWaitEvent(s1, evF, 0);

    const dim3 sblk(64, 4);
    const int  HK = HH * KK;
    const int  GG = VT / 64;     // 128

    for (int cch = 0; cch < 4; cch++) {
        k_scatter<<<dim3(VT / 4, 3), sblk, 0, s1>>>(x + cch * 3 * HH, TT * HH,
                                                    pFvX + (size_t)cch * 3 * VT * KK);
        k_gemm<3, 0, 1><<<GG * 3, 256, SM3, s1>>>(pFvX + (size_t)cch * 3 * VT * KK, pWt,
                                                  pBias, nullptr, nullptr,
                                                  pXG + (size_t)cch * 9 * VH, 0);
        cudaEventRecord(ev[cch], s1);
    }

    // ---- recurrent h-loop (main stream) ----
    for (int t = 0; t < TT; t++) {
        // ODE: a = elu(conv5(h)) ; ho = h + tanh(conv6(a))
        k_scatter<<<dim3(VT / 4, 1), sblk>>>(pH, HH, pFvH);
        k_gemm<1, 1, 0><<<GG, 256, SM1>>>(pFvH, pWt + 5 * HK, pBias + 5 * HH,
                                          nullptr, nullptr, pA, 0);
        k_scatter<<<dim3(VT / 4, 1), sblk>>>(pA, HH, pFvH);
        k_gemm<1, 2, 0><<<GG, 256, SM1>>>(pFvH, pWt + 6 * HK, pBias + 6 * HH,
                                          pH, nullptr, pHO, 0);
        // GRU: [hr|zh] = conv{1,3}(ho), gates fused in epilogue -> g_h + out
        k_scatter<<<dim3(VT / 4, 1), sblk>>>(pHO, HH, pFvH);
        if ((t % 3) == 0) cudaStreamWaitEvent(0, ev[t / 3], 0);
        k_gemm<2, 3, 0><<<GG, 256, SM2>>>(pFvH, pWt + 3 * HK, pBias + 3 * HH,
                                          pHO, pXG + (size_t)t * 3 * VH, out, t);
    }
}

// round 12
// speedup vs baseline: 1.1987x; 1.0169x over previous
#include <cuda_runtime.h>
#include <cuda_fp16.h>
#include <cstdint>
#include <math.h>

#define BB 4
#define VV 2048
#define TT 12
#define HH 64
#define EE 32768
#define VT (BB*VV)            /* 8192 */
#define TOTK 27
#define KK (TOTK*HH + HH)     /* 1792 */
#define NCONV 7
#define VH (VT*HH)

// ================= helpers =================
__device__ __forceinline__ uint32_t smem_u32(const void* p) {
    uint32_t a;
    asm("{ .reg .u64 t; cvta.to.shared.u64 t, %1; cvt.u32.u64 %0, t; }" : "=r"(a) : "l"(p));
    return a;
}
__device__ __forceinline__ void cp16(uint32_t dst, const void* src) {
    asm volatile("cp.async.ca.shared.global [%0], [%1], 16;" :: "r"(dst), "l"(src));
}
#define CP_COMMIT() asm volatile("cp.async.commit_group;" ::: "memory")
#define CP_WAIT0()  asm volatile("cp.async.wait_group 0;" ::: "memory")
#define CP_WAIT1()  asm volatile("cp.async.wait_group 1;" ::: "memory")
#define CP_WAIT2()  asm volatile("cp.async.wait_group 2;" ::: "memory")
#define BARH(id)    asm volatile("bar.sync %0, 128;" :: "r"((id) + 1) : "memory")

// ================= persistent device scratch =================
__device__ __align__(256) __half          g_FvH[VT * KK];              // 29.4 MB (h-side)
__device__ __align__(256) __half          g_FvX[(size_t)TT * VT * KK]; // 352 MB (x-side)
__device__ __align__(256) __half          g_WtH[NCONV * HH * KK];      // [perm conv][n][k]
__device__ __align__(256) float           g_biasP[NCONV * HH];
__device__ __align__(256) float           g_basis[EE * 8];
__device__ __align__(256) int             g_cell[EE];
// CSR-ordered edge tables
__device__ __align__(256) float           g_basisC[EE * 8];
__device__ __align__(256) int             g_scC[EE];                   // src | (cell<<16)
__device__ __align__(256) int             g_cnt[256 * VV];             // per-slice node counts
__device__ int            g_deg[VV];
__device__ float          g_deginv[VV];
__device__ int            g_csroff[VV + 1];
__device__ __align__(256) float g_h [VH];
__device__ __align__(256) float g_a [VH];
__device__ __align__(256) float g_ho[VH];
__device__ __align__(256) float g_xg[(size_t)TT * 3 * VH];  // [t][rx,zx,nx]

// ---------------- prep: weight pack (fp16) + spline basis/cell + zero h ----------------
__global__ void k_prep(const float* __restrict__ Wk, const float* __restrict__ Wroot,
                       const float* __restrict__ bias, const float* __restrict__ attr) {
    int idx = blockIdx.x * blockDim.x + threadIdx.x;
    if (idx < VH) g_h[idx] = 0.0f;
    if (idx < EE) {
        int e = idx;
        float fr[3]; int lo[3];
        #pragma unroll
        for (int d = 0; d < 3; d++) {
            float u  = attr[e * 3 + d] * 2.0f;
            float fl = fminf(fmaxf(floorf(u), 0.0f), 1.0f);
            fr[d] = u - fl;
            lo[d] = (int)fl;
        }
        #pragma unroll
        for (int s = 0; s < 8; s++) {
            int b0 = s & 1, b1 = (s >> 1) & 1, b2 = (s >> 2) & 1;
            float b = (b0 ? fr[0] : 1.0f - fr[0])
                    * (b1 ? fr[1] : 1.0f - fr[1])
                    * (b2 ? fr[2] : 1.0f - fr[2]);
            g_basis[e * 8 + s] = b;
        }
        g_cell[e] = lo[0] + 2 * lo[1] + 4 * lo[2];
    }
    if (idx >= NCONV * HH * KK) return;
    int k = idx % KK;
    int n = (idx / KK) & 63;
    int p = idx / (KK * HH);
    const int perm[7] = {0, 2, 4, 1, 3, 5, 6};
    int conv = perm[p];
    float v = (k < TOTK * HH) ? Wk[(conv * TOTK * HH + k) * HH + n]
                              : Wroot[(conv * HH + (k - TOTK * HH)) * HH + n];
    g_WtH[idx] = __float2half(v);
    if (k == 0) g_biasP[p * HH + n] = bias[conv * HH + n];
}

// ---------------- setup pass 1: per-slice (128 edges) per-node counts ----------------
__global__ void k_cnt(const int* __restrict__ eidx) {
    int e = blockIdx.x * blockDim.x + threadIdx.x;
    if (e < EE) atomicAdd(&g_cnt[(e >> 7) * VV + eidx[EE + e]], 1);
}

// ---------------- setup pass 2: per-node local prefixes over slices + totals ----------
__global__ void k_offs() {
    int v = blockIdx.x * blockDim.x + threadIdx.x;
    if (v >= VV) return;
    int run = 0;
    for (int bb = 0; bb < 256; bb++) {
        int tv = g_cnt[bb * VV + v];
        g_cnt[bb * VV + v] = run;
        run += tv;
    }
    g_deg[v] = run;
}

// ---------------- setup pass 3: CSR offsets via parallel scan (integer-exact) --------
__global__ void k_scan2() {
    __shared__ int ssum[1024];
    int tid = threadIdx.x;                      // 1024 threads, 2 nodes each
    int d0 = g_deg[2 * tid], d1 = g_deg[2 * tid + 1];
    ssum[tid] = d0 + d1;
    __syncthreads();
    #pragma unroll
    for (int off = 1; off < 1024; off <<= 1) {  // Kogge-Stone inclusive scan
        int v = (tid >= off) ? ssum[tid - off] : 0;
        __syncthreads();
        ssum[tid] += v;
        __syncthreads();
    }
    int base = (tid > 0) ? ssum[tid - 1] : 0;
    g_csroff[2 * tid]     = base;
    g_csroff[2 * tid + 1] = base + d0;
    g_deginv[2 * tid]     = 1.0f / (float)max(d0, 1);
    g_deginv[2 * tid + 1] = 1.0f / (float)max(d1, 1);
    if (tid == 1023) g_csroff[VV] = ssum[1023];
}

// ---------------- setup pass 4: fill tables in exact global edge order ----------------
__global__ void k_fill3(const int* __restrict__ eidx) {
    __shared__ int sbase[VV];
    int bb = blockIdx.x;                       // slice of 128 edges
    for (int v = threadIdx.x; v < VV; v += 256)
        sbase[v] = g_csroff[v] + g_cnt[bb * VV + v];
    __syncthreads();
    if (threadIdx.x >= 32) return;
    int lane = threadIdx.x;
    const int* dst = eidx + EE;
    #pragma unroll
    for (int r = 0; r < 4; r++) {
        int e = bb * 128 + r * 32 + lane;
        int d = dst[e];
        unsigned grp = __match_any_sync(0xFFFFFFFFu, d);
        int leader = __ffs(grp) - 1;
        int rank = __popc(grp & ((1u << lane) - 1u));
        int lb = 0;
        if (lane == leader) lb = sbase[d];
        lb = __shfl_sync(grp, lb, leader);
        int pos = lb + rank;
        if (lane == leader) sbase[d] = lb + __popc(grp);
        g_scC[pos] = eidx[e] | (g_cell[e] << 16);
        *(float4*)&g_basisC[pos * 8]     = *(const float4*)&g_basis[e * 8];
        *(float4*)&g_basisC[pos * 8 + 4] = *(const float4*)&g_basis[e * 8 + 4];
        __syncwarp();
    }
}

// ---------------- scatter: register accumulators + uniform cell switch ----------------
template <int L0, int L1, int L2>
__device__ __forceinline__ void upd(float* acc, const float* bas, float xs) {
    #pragma unroll
    for (int s = 0; s < 8; s++) {
        int k = (L0 + (s & 1)) + 3 * (L1 + ((s >> 1) & 1)) + 9 * (L2 + ((s >> 2) & 1));
        acc[k] = fmaf(bas[s], xs, acc[k]);
    }
}

__global__ void __launch_bounds__(256) k_scatter(const float* __restrict__ feat, int stride,
                                                 __half* __restrict__ dst) {
    int c    = threadIdx.x;
    int nsub = threadIdx.y;
    int node = blockIdx.x * 4 + nsub;
    int b = node >> 11;
    int v = node & (VV - 1);
    feat += (size_t)blockIdx.y * HH;
    dst  += (size_t)blockIdx.y * VT * KK;

    float acc[TOTK];
    #pragma unroll
    for (int k = 0; k < TOTK; k++) acc[k] = 0.0f;

    int i0 = g_csroff[v], i1 = g_csroff[v + 1];
    int base = b * VV;
    for (int ii = i0; ii < i1; ii++) {
        float4 bA = *(const float4*)&g_basisC[ii * 8];
        float4 bB = *(const float4*)&g_basisC[ii * 8 + 4];
        int    sc = g_scC[ii];
        float  xs = feat[(size_t)(base + (sc & 0xFFFF)) * stride + c];
        float bas[8] = {bA.x, bA.y, bA.z, bA.w, bB.x, bB.y, bB.z, bB.w};
        switch (sc >> 16) {
            case 0: upd<0,0,0>(acc, bas, xs); break;
            case 1: upd<1,0,0>(acc, bas, xs); break;
            case 2: upd<0,1,0>(acc, bas, xs); break;
            case 3: upd<1,1,0>(acc, bas, xs); break;
            case 4: upd<0,0,1>(acc, bas, xs); break;
            case 5: upd<1,0,1>(acc, bas, xs); break;
            case 6: upd<0,1,1>(acc, bas, xs); break;
            case 7: upd<1,1,1>(acc, bas, xs); break;
        }
    }
    float di = g_deginv[v];
    __half* o = dst + (size_t)node * KK + c;
    #pragma unroll
    for (int k = 0; k < TOTK; k++) o[k * HH] = __float2half(acc[k] * di);
    o[TOTK * HH] = __float2half(feat[(size_t)node * stride + c]);
}

// ---------------- FP16 mma GEMM: M=64, 256 thr, split-K halves, 3-stage pipeline ------
// Half p handles K-chunks ck ≡ p (mod 2); 3 cp.async stages per half, graded waits.
// EPI: 0 plain(+bias), 1 elu(+bias), 2 extra+tanh(+bias), 3 fused GRU gates (NG==2).
template <int NG, int EPI, int BATCH>
__global__ void __launch_bounds__(256) k_gemm(const __half* __restrict__ Ab,
                                              const __half* __restrict__ Bw,
                                              const float* __restrict__ bias,
                                              const float* __restrict__ extra,
                                              const float* __restrict__ xgt,
                                              float* __restrict__ out, int t) {
    extern __shared__ __half smem[];
    const int ABUF = 64 * 40;
    const int BBUF = NG * 64 * 40;

    const int tid  = threadIdx.x;
    const int half = tid >> 7;
    const int htid = tid & 127;
    const int m0   = blockIdx.x * 64;
    const int lane = tid & 31, wid = (tid >> 5) & 3;
    const int wm = (wid & 1) * 32, wn = (wid >> 1) * 32;
    const int g  = lane >> 2,  tq = lane & 3;

    __half* As = smem + half * (3 * ABUF);
    __half* Bs = smem + 6 * ABUF + half * (3 * BBUF);

    float c[NG][2][4][4];
    #pragma unroll
    for (int gg = 0; gg < NG; gg++)
        #pragma unroll
        for (int mt = 0; mt < 2; mt++)
            #pragma unroll
            for (int nt = 0; nt < 4; nt++)
                #pragma unroll
                for (int i = 0; i < 4; i++) c[gg][mt][nt][i] = 0.0f;

    const uint32_t sA = smem_u32(As);
    const uint32_t sB = smem_u32(Bs);

    auto load_tiles = [&](int kc, int st) {
        #pragma unroll
        for (int i = 0; i < 2; i++) {
            int seg = htid + i * 128;
            int row = seg >> 2, so = seg & 3;
            cp16(sA + (uint32_t)(st * ABUF + row * 40 + so * 8) * 2,
                 &Ab[(size_t)(m0 + row) * KK + kc * 32 + so * 8]);
        }
        #pragma unroll
        for (int i = 0; i < NG * 2; i++) {
            int seg = htid + i * 128;
            int row = seg >> 2, so = seg & 3;
            cp16(sB + (uint32_t)(st * BBUF + row * 40 + so * 8) * 2,
                 &Bw[(size_t)row * KK + kc * 32 + so * 8]);
        }
    };

    const int NIT = (KK / 32) / 2;   // 28 chunks per half
    load_tiles(half,     0); CP_COMMIT();
    load_tiles(half + 2, 1); CP_COMMIT();
    load_tiles(half + 4, 2); CP_COMMIT();

    for (int it = 0; it < NIT; it++) {
        const int rem = NIT - 1 - it;            // future stages still pending
        if (rem >= 2)      CP_WAIT2();           // stage `it` drained (FIFO retire)
        else if (rem == 1) CP_WAIT1();
        else               CP_WAIT0();
        BARH(half);
        const int buf = it % 3;
        #pragma unroll
        for (int kh = 0; kh < 2; kh++) {
            const int kb = kh * 16;
            uint32_t a[2][4];
            #pragma unroll
            for (int mt = 0; mt < 2; mt++) {
                int r0 = buf * ABUF + (wm + mt * 16 + g) * 40 + kb + 2 * tq;
                int r1 = r0 + 8 * 40;
                a[mt][0] = *(const uint32_t*)&As[r0];
                a[mt][1] = *(const uint32_t*)&As[r1];
                a[mt][2] = *(const uint32_t*)&As[r0 + 8];
                a[mt][3] = *(const uint32_t*)&As[r1 + 8];
            }
            #pragma unroll
            for (int gg = 0; gg < NG; gg++) {
                uint32_t b[4][2];
                #pragma unroll
                for (int nt = 0; nt < 4; nt++) {
                    int br = buf * BBUF + (gg * 64 + wn + nt * 8 + g) * 40 + kb + 2 * tq;
                    b[nt][0] = *(const uint32_t*)&Bs[br];
                    b[nt][1] = *(const uint32_t*)&Bs[br + 8];
                }
                #pragma unroll
                for (int mt = 0; mt < 2; mt++)
                    #pragma unroll
                    for (int nt = 0; nt < 4; nt++) {
                        float* cc = c[gg][mt][nt];
                        asm volatile(
                            "mma.sync.aligned.m16n8k16.row.col.f32.f16.f16.f32 "
                            "{%0,%1,%2,%3},{%4,%5,%6,%7},{%8,%9},{%0,%1,%2,%3};"
                            : "+f"(cc[0]), "+f"(cc[1]), "+f"(cc[2]), "+f"(cc[3])
                            : "r"(a[mt][0]), "r"(a[mt][1]), "r"(a[mt][2]), "r"(a[mt][3]),
                              "r"(b[nt][0]), "r"(b[nt][1]));
                    }
            }
        }
        BARH(half);
        if (it + 3 < NIT) { load_tiles(half + 2 * (it + 3), buf); CP_COMMIT(); }
    }

    // ---- cross-half reduction (padded stage: stride 32*NG+1 -> conflict-free) ----
    __syncthreads();
    float* red = (float*)smem;
    const int RP = 32 * NG + 1;
    if (half == 1) {
        float* r = &red[htid * RP];
        int ix = 0;
        #pragma unroll
        for (int gg = 0; gg < NG; gg++)
            #pragma unroll
            for (int mt = 0; mt < 2; mt++)
                #pragma unroll
                for (int nt = 0; nt < 4; nt++)
                    #pragma unroll
                    for (int i = 0; i < 4; i++) r[ix++] = c[gg][mt][nt][i];
    }
    __syncthreads();
    if (half == 1) return;
    {
        const float* r = &red[htid * RP];
        int ix = 0;
        #pragma unroll
        for (int gg = 0; gg < NG; gg++)
            #pragma unroll
            for (int mt = 0; mt < 2; mt++)
                #pragma unroll
                for (int nt = 0; nt < 4; nt++)
                    #pragma unroll
                    for (int i = 0; i < 4; i++) c[gg][mt][nt][i] += r[ix++];
    }

    // ---- epilogue (half 0 only) ----
    if constexpr (EPI == 3) {
        // fused GRU gates: gg0 = hr (conv1), gg1 = zh (conv3)
        #pragma unroll
        for (int mt = 0; mt < 2; mt++) {
            #pragma unroll
            for (int nt = 0; nt < 4; nt++) {
                int col = wn + nt * 8 + 2 * tq;
                float b00 = bias[col], b01 = bias[col + 1];
                float b10 = bias[64 + col], b11 = bias[64 + col + 1];
                #pragma unroll
                for (int hf = 0; hf < 2; hf++) {
                    int row = m0 + wm + mt * 16 + g + hf * 8;
                    int o2  = row * 64 + col;
                    float hr0 = c[0][mt][nt][hf * 2 + 0] + b00;
                    float hr1 = c[0][mt][nt][hf * 2 + 1] + b01;
                    float zh0 = c[1][mt][nt][hf * 2 + 0] + b10;
                    float zh1 = c[1][mt][nt][hf * 2 + 1] + b11;
                    float2 rx = *(const float2*)&xgt[o2];
                    float2 zx = *(const float2*)&xgt[VH + o2];
                    float2 nx = *(const float2*)&xgt[2 * VH + o2];
                    float2 ho = *(const float2*)&extra[o2];
                    float r0 = 1.0f / (1.0f + expf(-(rx.x + hr0)));
                    float r1 = 1.0f / (1.0f + expf(-(rx.y + hr1)));
                    float z0 = 1.0f / (1.0f + expf(-(zx.x + zh0)));
                    float z1 = 1.0f / (1.0f + expf(-(zx.y + zh1)));
                    float n0 = tanhf(nx.x + r0 * hr0);
                    float n1 = tanhf(nx.y + r1 * hr1);
                    float h0 = (1.0f - z0) * n0 + z0 * ho.x;
                    float h1 = (1.0f - z1) * n1 + z1 * ho.y;
                    *(float2*)&g_h[o2] = make_float2(h0, h1);
                    *(float2*)&out[((size_t)row * TT + t) * HH + col] = make_float2(h0, h1);
                }
            }
        }
    } else {
        #pragma unroll
        for (int gg = 0; gg < NG; gg++) {
            const float* biasg = bias + gg * 64;
            #pragma unroll
            for (int mt = 0; mt < 2; mt++) {
                #pragma unroll
                for (int nt = 0; nt < 4; nt++) {
                    int col = wn + nt * 8 + 2 * tq;
                    float b0 = biasg[col], b1 = biasg[col + 1];
                    #pragma unroll
                    for (int hf = 0; hf < 2; hf++) {
                        int row = m0 + wm + mt * 16 + g + hf * 8;
                        float v0 = c[gg][mt][nt][hf * 2 + 0] + b0;
                        float v1 = c[gg][mt][nt][hf * 2 + 1] + b1;
                        if (EPI == 1) {
                            v0 = (v0 > 0.0f) ? v0 : (expf(v0) - 1.0f);
                            v1 = (v1 > 0.0f) ? v1 : (expf(v1) - 1.0f);
                        }
                        size_t o;
                        if (BATCH) {
                            int tb = row >> 13, nd = row & (VT - 1);
                            o = ((size_t)(tb * NG + gg) * VT + nd) * 64 + col;
                        } else {
                            o = (size_t)gg * VH + (size_t)row * 64 + col;
                        }
                        if (EPI == 2) {
                            float2 e2 = *(const float2*)&extra[(size_t)row * 64 + col];
                            v0 = e2.x + tanhf(v0);
                            v1 = e2.y + tanhf(v1);
                        }
                        *(float2*)&out[o] = make_float2(v0, v1);
                    }
                }
            }
        }
    }
}

// ---------------- launch ----------------
extern "C" void kernel_launch(void* const* d_in, const int* in_sizes, int n_in,
                              void* d_out, int out_size) {
    const float* x     = (const float*)d_in[0];
    const float* attr  = (const float*)d_in[1];
    const float* Wk    = (const float*)d_in[2];
    const float* Wroot = (const float*)d_in[3];
    const float* bias  = (const float*)d_in[4];
    const int*   eidx  = (const int*)d_in[5];
    float*       out   = (float*)d_out;

    __half *pWt, *pFvH, *pFvX;
    float *pBias, *pH, *pA, *pHO, *pXG;
    int   *pCnt;
    cudaGetSymbolAddress((void**)&pWt,   g_WtH);
    cudaGetSymbolAddress((void**)&pFvH,  g_FvH);
    cudaGetSymbolAddress((void**)&pFvX,  g_FvX);
    cudaGetSymbolAddress((void**)&pBias, g_biasP);
    cudaGetSymbolAddress((void**)&pH,    g_h);
    cudaGetSymbolAddress((void**)&pA,    g_a);
    cudaGetSymbolAddress((void**)&pHO,   g_ho);
    cudaGetSymbolAddress((void**)&pXG,   g_xg);
    cudaGetSymbolAddress((void**)&pCnt,  g_cnt);

    // smem: 6 A stages + 6 B stages (3 per half), halfs -> bytes
    const int SM1 = (6 * 64 * 40 + 6 * 1 * 64 * 40) * 2;   // 61440
    const int SM2 = (6 * 64 * 40 + 6 * 2 * 64 * 40) * 2;   // 92160
    const int SM3 = (6 * 64 * 40 + 6 * 3 * 64 * 40) * 2;   // 122880
    cudaFuncSetAttribute(k_gemm<1, 1, 0>, cudaFuncAttributeMaxDynamicSharedMemorySize, SM1);
    cudaFuncSetAttribute(k_gemm<1, 2, 0>, cudaFuncAttributeMaxDynamicSharedMemorySize, SM1);
    cudaFuncSetAttribute(k_gemm<2, 3, 0>, cudaFuncAttributeMaxDynamicSharedMemorySize, SM2);
    cudaFuncSetAttribute(k_gemm<3, 0, 1>, cudaFuncAttributeMaxDynamicSharedMemorySize, SM3);

    // ---- setup (every call; deterministic) ----
    cudaMemsetAsync(pCnt, 0, 256 * VV * sizeof(int));
    k_prep <<<(NCONV * HH * KK + 255) / 256, 256>>>(Wk, Wroot, bias, attr);
    k_cnt  <<<EE / 256, 256>>>(eidx);
    k_offs <<<VV / 256, 256>>>();
    k_scan2<<<1, 1024>>>();
    k_fill3<<<256, 256>>>(eidx);

    // ---- fork: x-side (scatter + batched GEMM) in 4 chunks of 3 timesteps ----
    cudaStream_t s1;
    cudaStreamCreateWithFlags(&s1, cudaStreamNonBlocking);
    cudaEvent_t evF, ev[4];
    cudaEventCreateWithFlags(&evF, cudaEventDisableTiming);
    for (int i = 0; i < 4; i++) cudaEventCreateWithFlags(&ev[i], cudaEventDisableTiming);

    cudaEventRecord(evF, 0);
    cudaStreamWaitEvent(s1, evF, 0);

    const dim3 sblk(64, 4);
    const int  HK = HH * KK;
    const int  GG = VT / 64;     // 128

    for (int cch = 0; cch < 4; cch++) {
        k_scatter<<<dim3(VT / 4, 3), sblk, 0, s1>>>(x + cch * 3 * HH, TT * HH,
                                                    pFvX + (size_t)cch * 3 * VT * KK);
        k_gemm<3, 0, 1><<<GG * 3, 256, SM3, s1>>>(pFvX + (size_t)cch * 3 * VT * KK, pWt,
                                                  pBias, nullptr, nullptr,
                                                  pXG + (size_t)cch * 9 * VH, 0);
        cudaEventRecord(ev[cch], s1);
    }

    // ---- recurrent h-loop (main stream) ----
    for (int t = 0; t < TT; t++) {
        // ODE: a = elu(conv5(h)) ; ho = h + tanh(conv6(a))
        k_scatter<<<dim3(VT / 4, 1), sblk>>>(pH, HH, pFvH);
        k_gemm<1, 1, 0><<<GG, 256, SM1>>>(pFvH, pWt + 5 * HK, pBias + 5 * HH,
                                          nullptr, nullptr, pA, 0);
        k_scatter<<<dim3(VT / 4, 1), sblk>>>(pA, HH, pFvH);
        k_gemm<1, 2, 0><<<GG, 256, SM1>>>(pFvH, pWt + 6 * HK, pBias + 6 * HH,
                                          pH, nullptr, pHO, 0);
        // GRU: [hr|zh] = conv{1,3}(ho), gates fused in epilogue -> g_h + out
        k_scatter<<<dim3(VT / 4, 1), sblk>>>(pHO, HH, pFvH);
        if ((t % 3) == 0) cudaStreamWaitEvent(0, ev[t / 3], 0);
        k_gemm<2, 3, 0><<<GG, 256, SM2>>>(pFvH, pWt + 3 * HK, pBias + 3 * HH,
                                          pHO, pXG + (size_t)t * 3 * VH, out, t);
    }
}

// round 13
// speedup vs baseline: 1.1996x; 1.0008x over previous
#include <cuda_runtime.h>
#include <cuda_fp16.h>
#include <cstdint>
#include <math.h>

#define BB 4
#define VV 2048
#define TT 12
#define HH 64
#define EE 32768
#define VT (BB*VV)            /* 8192 */
#define TOTK 27
#define KK (TOTK*HH + HH)     /* 1792 */
#define NCONV 7
#define VH (VT*HH)

// ================= helpers =================
__device__ __forceinline__ uint32_t smem_u32(const void* p) {
    uint32_t a;
    asm("{ .reg .u64 t; cvta.to.shared.u64 t, %1; cvt.u32.u64 %0, t; }" : "=r"(a) : "l"(p));
    return a;
}
__device__ __forceinline__ void cp16(uint32_t dst, const void* src) {
    asm volatile("cp.async.ca.shared.global [%0], [%1], 16;" :: "r"(dst), "l"(src));
}
#define CP_COMMIT() asm volatile("cp.async.commit_group;" ::: "memory")
#define CP_WAIT0()  asm volatile("cp.async.wait_group 0;" ::: "memory")
#define CP_WAIT1()  asm volatile("cp.async.wait_group 1;" ::: "memory")
#define CP_WAIT2()  asm volatile("cp.async.wait_group 2;" ::: "memory")
#define BARH(id)    asm volatile("bar.sync %0, 128;" :: "r"((id) + 1) : "memory")

// ================= persistent device scratch =================
__device__ __align__(256) __half          g_FvH[VT * KK];              // 29.4 MB (h-side)
__device__ __align__(256) __half          g_FvX[(size_t)TT * VT * KK]; // 352 MB (x-side)
__device__ __align__(256) __half          g_WtH[NCONV * HH * KK];      // [perm conv][n][k]
__device__ __align__(256) float           g_biasP[NCONV * HH];
__device__ __align__(256) float           g_basis[EE * 8];
__device__ __align__(256) int             g_cell[EE];
// CSR-ordered edge tables
__device__ __align__(256) float           g_basisC[EE * 8];
__device__ __align__(256) int             g_scC[EE];                   // src | (cell<<16)
__device__ __align__(256) int             g_cnt[256 * VV];             // per-slice node counts
__device__ int            g_deg[VV];
__device__ float          g_deginv[VV];
__device__ int            g_csroff[VV + 1];
__device__ __align__(256) float g_h [VH];
__device__ __align__(256) float g_a [VH];
__device__ __align__(256) float g_ho[VH];
__device__ __align__(256) float g_xg[(size_t)TT * 3 * VH];  // [t][rx,zx,nx]

// ---------------- prep: weight pack (fp16) + spline basis/cell + zero h ----------------
__global__ void k_prep(const float* __restrict__ Wk, const float* __restrict__ Wroot,
                       const float* __restrict__ bias, const float* __restrict__ attr) {
    int idx = blockIdx.x * blockDim.x + threadIdx.x;
    if (idx < VH) g_h[idx] = 0.0f;
    if (idx < EE) {
        int e = idx;
        float fr[3]; int lo[3];
        #pragma unroll
        for (int d = 0; d < 3; d++) {
            float u  = attr[e * 3 + d] * 2.0f;
            float fl = fminf(fmaxf(floorf(u), 0.0f), 1.0f);
            fr[d] = u - fl;
            lo[d] = (int)fl;
        }
        #pragma unroll
        for (int s = 0; s < 8; s++) {
            int b0 = s & 1, b1 = (s >> 1) & 1, b2 = (s >> 2) & 1;
            float b = (b0 ? fr[0] : 1.0f - fr[0])
                    * (b1 ? fr[1] : 1.0f - fr[1])
                    * (b2 ? fr[2] : 1.0f - fr[2]);
            g_basis[e * 8 + s] = b;
        }
        g_cell[e] = lo[0] + 2 * lo[1] + 4 * lo[2];
    }
    if (idx >= NCONV * HH * KK) return;
    int k = idx % KK;
    int n = (idx / KK) & 63;
    int p = idx / (KK * HH);
    const int perm[7] = {0, 2, 4, 1, 3, 5, 6};
    int conv = perm[p];
    float v = (k < TOTK * HH) ? Wk[(conv * TOTK * HH + k) * HH + n]
                              : Wroot[(conv * HH + (k - TOTK * HH)) * HH + n];
    g_WtH[idx] = __float2half(v);
    if (k == 0) g_biasP[p * HH + n] = bias[conv * HH + n];
}

// ---------------- setup pass 1: per-slice (128 edges) per-node counts ----------------
__global__ void k_cnt(const int* __restrict__ eidx) {
    int e = blockIdx.x * blockDim.x + threadIdx.x;
    if (e < EE) atomicAdd(&g_cnt[(e >> 7) * VV + eidx[EE + e]], 1);
}

// ---------------- setup pass 2: per-node local prefixes over slices + totals ----------
__global__ void k_offs() {
    int v = blockIdx.x * blockDim.x + threadIdx.x;
    if (v >= VV) return;
    int run = 0;
    for (int bb = 0; bb < 256; bb++) {
        int tv = g_cnt[bb * VV + v];
        g_cnt[bb * VV + v] = run;
        run += tv;
    }
    g_deg[v] = run;
}

// ---------------- setup pass 3: CSR offsets via parallel scan (integer-exact) --------
__global__ void k_scan2() {
    __shared__ int ssum[1024];
    int tid = threadIdx.x;                      // 1024 threads, 2 nodes each
    int d0 = g_deg[2 * tid], d1 = g_deg[2 * tid + 1];
    ssum[tid] = d0 + d1;
    __syncthreads();
    #pragma unroll
    for (int off = 1; off < 1024; off <<= 1) {  // Kogge-Stone inclusive scan
        int v = (tid >= off) ? ssum[tid - off] : 0;
        __syncthreads();
        ssum[tid] += v;
        __syncthreads();
    }
    int base = (tid > 0) ? ssum[tid - 1] : 0;
    g_csroff[2 * tid]     = base;
    g_csroff[2 * tid + 1] = base + d0;
    g_deginv[2 * tid]     = 1.0f / (float)max(d0, 1);
    g_deginv[2 * tid + 1] = 1.0f / (float)max(d1, 1);
    if (tid == 1023) g_csroff[VV] = ssum[1023];
}

// ---------------- setup pass 4: fill tables in exact global edge order ----------------
__global__ void k_fill3(const int* __restrict__ eidx) {
    __shared__ int sbase[VV];
    int bb = blockIdx.x;                       // slice of 128 edges
    for (int v = threadIdx.x; v < VV; v += 256)
        sbase[v] = g_csroff[v] + g_cnt[bb * VV + v];
    __syncthreads();
    if (threadIdx.x >= 32) return;
    int lane = threadIdx.x;
    const int* dst = eidx + EE;
    #pragma unroll
    for (int r = 0; r < 4; r++) {
        int e = bb * 128 + r * 32 + lane;
        int d = dst[e];
        unsigned grp = __match_any_sync(0xFFFFFFFFu, d);
        int leader = __ffs(grp) - 1;
        int rank = __popc(grp & ((1u << lane) - 1u));
        int lb = 0;
        if (lane == leader) lb = sbase[d];
        lb = __shfl_sync(grp, lb, leader);
        int pos = lb + rank;
        if (lane == leader) sbase[d] = lb + __popc(grp);
        g_scC[pos] = eidx[e] | (g_cell[e] << 16);
        *(float4*)&g_basisC[pos * 8]     = *(const float4*)&g_basis[e * 8];
        *(float4*)&g_basisC[pos * 8 + 4] = *(const float4*)&g_basis[e * 8 + 4];
        __syncwarp();
    }
}

// ---------------- scatter: register accumulators + uniform cell switch ----------------
template <int L0, int L1, int L2>
__device__ __forceinline__ void upd(float* acc, const float* bas, float xs) {
    #pragma unroll
    for (int s = 0; s < 8; s++) {
        int k = (L0 + (s & 1)) + 3 * (L1 + ((s >> 1) & 1)) + 9 * (L2 + ((s >> 2) & 1));
        acc[k] = fmaf(bas[s], xs, acc[k]);
    }
}

__global__ void __launch_bounds__(256) k_scatter(const float* __restrict__ feat, int stride,
                                                 __half* __restrict__ dst) {
    int c    = threadIdx.x;
    int nsub = threadIdx.y;
    int node = blockIdx.x * 4 + nsub;
    int b = node >> 11;
    int v = node & (VV - 1);
    feat += (size_t)blockIdx.y * HH;
    dst  += (size_t)blockIdx.y * VT * KK;

    float acc[TOTK];
    #pragma unroll
    for (int k = 0; k < TOTK; k++) acc[k] = 0.0f;

    int i0 = g_csroff[v], i1 = g_csroff[v + 1];
    int base = b * VV;
    for (int ii = i0; ii < i1; ii++) {
        float4 bA = *(const float4*)&g_basisC[ii * 8];
        float4 bB = *(const float4*)&g_basisC[ii * 8 + 4];
        int    sc = g_scC[ii];
        float  xs = feat[(size_t)(base + (sc & 0xFFFF)) * stride + c];
        float bas[8] = {bA.x, bA.y, bA.z, bA.w, bB.x, bB.y, bB.z, bB.w};
        switch (sc >> 16) {
            case 0: upd<0,0,0>(acc, bas, xs); break;
            case 1: upd<1,0,0>(acc, bas, xs); break;
            case 2: upd<0,1,0>(acc, bas, xs); break;
            case 3: upd<1,1,0>(acc, bas, xs); break;
            case 4: upd<0,0,1>(acc, bas, xs); break;
            case 5: upd<1,0,1>(acc, bas, xs); break;
            case 6: upd<0,1,1>(acc, bas, xs); break;
            case 7: upd<1,1,1>(acc, bas, xs); break;
        }
    }
    float di = g_deginv[v];
    __half* o = dst + (size_t)node * KK + c;
    #pragma unroll
    for (int k = 0; k < TOTK; k++) o[k * HH] = __float2half(acc[k] * di);
    o[TOTK * HH] = __float2half(feat[(size_t)node * stride + c]);
}

// ---------------- FP16 mma GEMM: M=64, 256 thr, split-K halves, 3-stage pipeline ------
// Half p handles K-chunks ck ≡ p (mod 2); 3 cp.async stages per half, graded waits.
// EPI: 0 plain(+bias), 1 elu(+bias), 2 extra+tanh(+bias), 3 fused GRU gates (NG==2).
template <int NG, int EPI, int BATCH>
__global__ void __launch_bounds__(256) k_gemm(const __half* __restrict__ Ab,
                                              const __half* __restrict__ Bw,
                                              const float* __restrict__ bias,
                                              const float* __restrict__ extra,
                                              const float* __restrict__ xgt,
                                              float* __restrict__ out, int t) {
    extern __shared__ __half smem[];
    const int ABUF = 64 * 40;
    const int BBUF = NG * 64 * 40;

    const int tid  = threadIdx.x;
    const int half = tid >> 7;
    const int htid = tid & 127;
    const int m0   = blockIdx.x * 64;
    const int lane = tid & 31, wid = (tid >> 5) & 3;
    const int wm = (wid & 1) * 32, wn = (wid >> 1) * 32;
    const int g  = lane >> 2,  tq = lane & 3;

    __half* As = smem + half * (3 * ABUF);
    __half* Bs = smem + 6 * ABUF + half * (3 * BBUF);

    float c[NG][2][4][4];
    #pragma unroll
    for (int gg = 0; gg < NG; gg++)
        #pragma unroll
        for (int mt = 0; mt < 2; mt++)
            #pragma unroll
            for (int nt = 0; nt < 4; nt++)
                #pragma unroll
                for (int i = 0; i < 4; i++) c[gg][mt][nt][i] = 0.0f;

    const uint32_t sA = smem_u32(As);
    const uint32_t sB = smem_u32(Bs);

    auto load_tiles = [&](int kc, int st) {
        #pragma unroll
        for (int i = 0; i < 2; i++) {
            int seg = htid + i * 128;
            int row = seg >> 2, so = seg & 3;
            cp16(sA + (uint32_t)(st * ABUF + row * 40 + so * 8) * 2,
                 &Ab[(size_t)(m0 + row) * KK + kc * 32 + so * 8]);
        }
        #pragma unroll
        for (int i = 0; i < NG * 2; i++) {
            int seg = htid + i * 128;
            int row = seg >> 2, so = seg & 3;
            cp16(sB + (uint32_t)(st * BBUF + row * 40 + so * 8) * 2,
                 &Bw[(size_t)row * KK + kc * 32 + so * 8]);
        }
    };

    const int NIT = (KK / 32) / 2;   // 28 chunks per half
    load_tiles(half,     0); CP_COMMIT();
    load_tiles(half + 2, 1); CP_COMMIT();
    load_tiles(half + 4, 2); CP_COMMIT();

    for (int it = 0; it < NIT; it++) {
        const int rem = NIT - 1 - it;            // future stages still pending
        if (rem >= 2)      CP_WAIT2();           // stage `it` drained (FIFO retire)
        else if (rem == 1) CP_WAIT1();
        else               CP_WAIT0();
        BARH(half);
        const int buf = it % 3;
        #pragma unroll
        for (int kh = 0; kh < 2; kh++) {
            const int kb = kh * 16;
            uint32_t a[2][4];
            #pragma unroll
            for (int mt = 0; mt < 2; mt++) {
                int r0 = buf * ABUF + (wm + mt * 16 + g) * 40 + kb + 2 * tq;
                int r1 = r0 + 8 * 40;
                a[mt][0] = *(const uint32_t*)&As[r0];
                a[mt][1] = *(const uint32_t*)&As[r1];
                a[mt][2] = *(const uint32_t*)&As[r0 + 8];
                a[mt][3] = *(const uint32_t*)&As[r1 + 8];
            }
            #pragma unroll
            for (int gg = 0; gg < NG; gg++) {
                uint32_t b[4][2];
                #pragma unroll
                for (int nt = 0; nt < 4; nt++) {
                    int br = buf * BBUF + (gg * 64 + wn + nt * 8 + g) * 40 + kb + 2 * tq;
                    b[nt][0] = *(const uint32_t*)&Bs[br];
                    b[nt][1] = *(const uint32_t*)&Bs[br + 8];
                }
                #pragma unroll
                for (int mt = 0; mt < 2; mt++)
                    #pragma unroll
                    for (int nt = 0; nt < 4; nt++) {
                        float* cc = c[gg][mt][nt];
                        asm volatile(
                            "mma.sync.aligned.m16n8k16.row.col.f32.f16.f16.f32 "
                            "{%0,%1,%2,%3},{%4,%5,%6,%7},{%8,%9},{%0,%1,%2,%3};"
                            : "+f"(cc[0]), "+f"(cc[1]), "+f"(cc[2]), "+f"(cc[3])
                            : "r"(a[mt][0]), "r"(a[mt][1]), "r"(a[mt][2]), "r"(a[mt][3]),
                              "r"(b[nt][0]), "r"(b[nt][1]));
                    }
            }
        }
        BARH(half);
        if (it + 3 < NIT) { load_tiles(half + 2 * (it + 3), buf); CP_COMMIT(); }
    }

    // ---- cross-half reduction (padded stage: stride 32*NG+1 -> conflict-free) ----
    __syncthreads();
    float* red = (float*)smem;
    const int RP = 32 * NG + 1;
    if (half == 1) {
        float* r = &red[htid * RP];
        int ix = 0;
        #pragma unroll
        for (int gg = 0; gg < NG; gg++)
            #pragma unroll
            for (int mt = 0; mt < 2; mt++)
                #pragma unroll
                for (int nt = 0; nt < 4; nt++)
                    #pragma unroll
                    for (int i = 0; i < 4; i++) r[ix++] = c[gg][mt][nt][i];
    }
    __syncthreads();
    if (half == 1) return;
    {
        const float* r = &red[htid * RP];
        int ix = 0;
        #pragma unroll
        for (int gg = 0; gg < NG; gg++)
            #pragma unroll
            for (int mt = 0; mt < 2; mt++)
                #pragma unroll
                for (int nt = 0; nt < 4; nt++)
                    #pragma unroll
                    for (int i = 0; i < 4; i++) c[gg][mt][nt][i] += r[ix++];
    }

    // ---- epilogue (half 0 only) ----
    if constexpr (EPI == 3) {
        // fused GRU gates: gg0 = hr (conv1), gg1 = zh (conv3)
        #pragma unroll
        for (int mt = 0; mt < 2; mt++) {
            #pragma unroll
            for (int nt = 0; nt < 4; nt++) {
                int col = wn + nt * 8 + 2 * tq;
                float b00 = bias[col], b01 = bias[col + 1];
                float b10 = bias[64 + col], b11 = bias[64 + col + 1];
                #pragma unroll
                for (int hf = 0; hf < 2; hf++) {
                    int row = m0 + wm + mt * 16 + g + hf * 8;
                    int o2  = row * 64 + col;
                    float hr0 = c[0][mt][nt][hf * 2 + 0] + b00;
                    float hr1 = c[0][mt][nt][hf * 2 + 1] + b01;
                    float zh0 = c[1][mt][nt][hf * 2 + 0] + b10;
                    float zh1 = c[1][mt][nt][hf * 2 + 1] + b11;
                    float2 rx = *(const float2*)&xgt[o2];
                    float2 zx = *(const float2*)&xgt[VH + o2];
                    float2 nx = *(const float2*)&xgt[2 * VH + o2];
                    float2 ho = *(const float2*)&extra[o2];
                    float r0 = 1.0f / (1.0f + expf(-(rx.x + hr0)));
                    float r1 = 1.0f / (1.0f + expf(-(rx.y + hr1)));
                    float z0 = 1.0f / (1.0f + expf(-(zx.x + zh0)));
                    float z1 = 1.0f / (1.0f + expf(-(zx.y + zh1)));
                    float n0 = tanhf(nx.x + r0 * hr0);
                    float n1 = tanhf(nx.y + r1 * hr1);
                    float h0 = (1.0f - z0) * n0 + z0 * ho.x;
                    float h1 = (1.0f - z1) * n1 + z1 * ho.y;
                    *(float2*)&g_h[o2] = make_float2(h0, h1);
                    *(float2*)&out[((size_t)row * TT + t) * HH + col] = make_float2(h0, h1);
                }
            }
        }
    } else {
        #pragma unroll
        for (int gg = 0; gg < NG; gg++) {
            const float* biasg = bias + gg * 64;
            #pragma unroll
            for (int mt = 0; mt < 2; mt++) {
                #pragma unroll
                for (int nt = 0; nt < 4; nt++) {
                    int col = wn + nt * 8 + 2 * tq;
                    float b0 = biasg[col], b1 = biasg[col + 1];
                    #pragma unroll
                    for (int hf = 0; hf < 2; hf++) {
                        int row = m0 + wm + mt * 16 + g + hf * 8;
                        float v0 = c[gg][mt][nt][hf * 2 + 0] + b0;
                        float v1 = c[gg][mt][nt][hf * 2 + 1] + b1;
                        if (EPI == 1) {
                            v0 = (v0 > 0.0f) ? v0 : (expf(v0) - 1.0f);
                            v1 = (v1 > 0.0f) ? v1 : (expf(v1) - 1.0f);
                        }
                        size_t o;
                        if (BATCH) {
                            int tb = row >> 13, nd = row & (VT - 1);
                            o = ((size_t)(tb * NG + gg) * VT + nd) * 64 + col;
                        } else {
                            o = (size_t)gg * VH + (size_t)row * 64 + col;
                        }
                        if (EPI == 2) {
                            float2 e2 = *(const float2*)&extra[(size_t)row * 64 + col];
                            v0 = e2.x + tanhf(v0);
                            v1 = e2.y + tanhf(v1);
                        }
                        *(float2*)&out[o] = make_float2(v0, v1);
                    }
                }
            }
        }
    }
}

// ---------------- launch ----------------
extern "C" void kernel_launch(void* const* d_in, const int* in_sizes, int n_in,
                              void* d_out, int out_size) {
    const float* x     = (const float*)d_in[0];
    const float* attr  = (const float*)d_in[1];
    const float* Wk    = (const float*)d_in[2];
    const float* Wroot = (const float*)d_in[3];
    const float* bias  = (const float*)d_in[4];
    const int*   eidx  = (const int*)d_in[5];
    float*       out   = (float*)d_out;

    __half *pWt, *pFvH, *pFvX;
    float *pBias, *pH, *pA, *pHO, *pXG;
    int   *pCnt;
    cudaGetSymbolAddress((void**)&pWt,   g_WtH);
    cudaGetSymbolAddress((void**)&pFvH,  g_FvH);
    cudaGetSymbolAddress((void**)&pFvX,  g_FvX);
    cudaGetSymbolAddress((void**)&pBias, g_biasP);
    cudaGetSymbolAddress((void**)&pH,    g_h);
    cudaGetSymbolAddress((void**)&pA,    g_a);
    cudaGetSymbolAddress((void**)&pHO,   g_ho);
    cudaGetSymbolAddress((void**)&pXG,   g_xg);
    cudaGetSymbolAddress((void**)&pCnt,  g_cnt);

    // smem: 6 A stages + 6 B stages (3 per half), halfs -> bytes
    const int SM1 = (6 * 64 * 40 + 6 * 1 * 64 * 40) * 2;   // 61440
    const int SM2 = (6 * 64 * 40 + 6 * 2 * 64 * 40) * 2;   // 92160
    const int SM3 = (6 * 64 * 40 + 6 * 3 * 64 * 40) * 2;   // 122880
    cudaFuncSetAttribute(k_gemm<1, 1, 0>, cudaFuncAttributeMaxDynamicSharedMemorySize, SM1);
    cudaFuncSetAttribute(k_gemm<1, 2, 0>, cudaFuncAttributeMaxDynamicSharedMemorySize, SM1);
    cudaFuncSetAttribute(k_gemm<2, 3, 0>, cudaFuncAttributeMaxDynamicSharedMemorySize, SM2);
    cudaFuncSetAttribute(k_gemm<3, 0, 1>, cudaFuncAttributeMaxDynamicSharedMemorySize, SM3);

    // ---- setup (every call; deterministic) ----
    cudaMemsetAsync(pCnt, 0, 256 * VV * sizeof(int));
    k_prep <<<(NCONV * HH * KK + 255) / 256, 256>>>(Wk, Wroot, bias, attr);
    k_cnt  <<<EE / 256, 256>>>(eidx);
    k_offs <<<VV / 256, 256>>>();
    k_scan2<<<1, 1024>>>();
    k_fill3<<<256, 256>>>(eidx);

    // ---- fork: x-side (scatter + batched GEMM) in 4 chunks of 3 timesteps ----
    cudaStream_t s1;
    cudaStreamCreateWithFlags(&s1, cudaStreamNonBlocking);
    cudaEvent_t evF, ev[4];
    cudaEventCreateWithFlags(&evF, cudaEventDisableTiming);
    for (int i = 0; i < 4; i++) cudaEventCreateWithFlags(&ev[i], cudaEventDisableTiming);

    cudaEventRecord(evF, 0);
    cudaStreamWaitEvent(s1, evF, 0);

    const dim3 sblk(64, 4);
    const int  HK = HH * KK;
    const int  GG = VT / 64;     // 128

    for (int cch = 0; cch < 4; cch++) {
        k_scatter<<<dim3(VT / 4, 3), sblk, 0, s1>>>(x + cch * 3 * HH, TT * HH,
                                                    pFvX + (size_t)cch * 3 * VT * KK);
        k_gemm<3, 0, 1><<<GG * 3, 256, SM3, s1>>>(pFvX + (size_t)cch * 3 * VT * KK, pWt,
                                                  pBias, nullptr, nullptr,
                                                  pXG + (size_t)cch * 9 * VH, 0);
        cudaEventRecord(ev[cch], s1);
    }

    // ---- recurrent h-loop (main stream) ----
    for (int t = 0; t < TT; t++) {
        // ODE: a = elu(conv5(h)) ; ho = h + tanh(conv6(a))
        k_scatter<<<dim3(VT / 4, 1), sblk>>>(pH, HH, pFvH);
        k_gemm<1, 1, 0><<<GG, 256, SM1>>>(pFvH, pWt + 5 * HK, pBias + 5 * HH,
                                          nullptr, nullptr, pA, 0);
        k_scatter<<<dim3(VT / 4, 1), sblk>>>(pA, HH, pFvH);
        k_gemm<1, 2, 0><<<GG, 256, SM1>>>(pFvH, pWt + 6 * HK, pBias + 6 * HH,
                                          pH, nullptr, pHO, 0);
        // GRU: [hr|zh] = conv{1,3}(ho), gates fused in epilogue -> g_h + out
        k_scatter<<<dim3(VT / 4, 1), sblk>>>(pHO, HH, pFvH);
        if ((t % 3) == 0) cudaStreamWaitEvent(0, ev[t / 3], 0);
        k_gemm<2, 3, 0><<<GG, 256, SM2>>>(pFvH, pWt + 3 * HK, pBias + 3 * HH,
                                          pHO, pXG + (size_t)t * 3 * VH, out, t);
    }
}